// round 1
// baseline (speedup 1.0000x reference)
#include <cuda_runtime.h>
#include <mma.h>
#include <math.h>

using namespace nvcuda;

#define BB 16
#define SS 784
#define DD 768
#define HH 12
#define DHH 64
#define M_TOT (BB*SS)

// Scratch (device globals: allocation-free rule)
__device__ float g_q[BB*HH*SS*DHH];
__device__ float g_k[BB*HH*SS*DHH];
__device__ float g_v[BB*HH*SS*DHH];
__device__ float g_ctx[BB*SS*DD];

// ---------------------------------------------------------------------------
// GEMM: out = A[M,768] @ W[768,768]^T + bias   (y[m,n] = sum_k A[m,k]*W[n,k])
// mode 0: write to [B,H,S,DH] layout (head-split), optional fused RoPE
// mode 1: write plain [m*768+n]
// Block tile 128x64, BK=32, 256 threads (8 warps, 4x2 of 32x32 warp tiles)
// ---------------------------------------------------------------------------
__global__ __launch_bounds__(256) void gemm_kernel(
    const float* __restrict__ A, const float* __restrict__ W,
    const float* __restrict__ bias, const float* __restrict__ rope,
    float* __restrict__ out, int mode, int do_rope)
{
    extern __shared__ float sm[];
    float* a_s = sm;               // 128 x 36
    float* b_s = sm + 128*36;      // 64 x 36
    float* stg = sm;               // 128 x 68 (reused after mainloop)

    const int tid  = threadIdx.x;
    const int warp = tid >> 5;
    const int wm   = warp >> 1;    // 0..3
    const int wn   = warp & 1;     // 0..1
    const int m0   = blockIdx.y * 128;
    const int n0   = blockIdx.x * 64;

    wmma::fragment<wmma::accumulator,16,16,8,float> acc[2][2];
    #pragma unroll
    for (int i=0;i<2;i++)
        #pragma unroll
        for (int j=0;j<2;j++)
            wmma::fill_fragment(acc[i][j], 0.f);

    for (int k0 = 0; k0 < 768; k0 += 32) {
        // A tile: 128 rows x 32 cols
        #pragma unroll
        for (int i=0;i<4;i++){
            int lin = tid + i*256;
            int row = lin >> 3, c4 = (lin & 7) * 4;
            float4 v = *(const float4*)(A + (size_t)(m0+row)*768 + k0 + c4);
            *(float4*)(a_s + row*36 + c4) = v;
        }
        // W tile: 64 rows (n) x 32 cols (k)
        #pragma unroll
        for (int i=0;i<2;i++){
            int lin = tid + i*256;
            int row = lin >> 3, c4 = (lin & 7) * 4;
            float4 v = *(const float4*)(W + (size_t)(n0+row)*768 + k0 + c4);
            *(float4*)(b_s + row*36 + c4) = v;
        }
        __syncthreads();

        #pragma unroll
        for (int kk=0;kk<4;kk++){
            wmma::fragment<wmma::matrix_a,16,16,8,wmma::precision::tf32,wmma::row_major> af[2];
            wmma::fragment<wmma::matrix_b,16,16,8,wmma::precision::tf32,wmma::col_major> bf[2];
            #pragma unroll
            for (int i=0;i<2;i++){
                wmma::load_matrix_sync(af[i], a_s + (wm*32 + i*16)*36 + kk*8, 36);
                #pragma unroll
                for (int t=0;t<af[i].num_elements;t++) af[i].x[t] = wmma::__float_to_tf32(af[i].x[t]);
            }
            #pragma unroll
            for (int j=0;j<2;j++){
                wmma::load_matrix_sync(bf[j], b_s + (wn*32 + j*16)*36 + kk*8, 36);
                #pragma unroll
                for (int t=0;t<bf[j].num_elements;t++) bf[j].x[t] = wmma::__float_to_tf32(bf[j].x[t]);
            }
            #pragma unroll
            for (int i=0;i<2;i++)
                #pragma unroll
                for (int j=0;j<2;j++)
                    wmma::mma_sync(acc[i][j], af[i], bf[j], acc[i][j]);
        }
        __syncthreads();
    }

    // stage accumulators (128 x 68)
    #pragma unroll
    for (int i=0;i<2;i++)
        #pragma unroll
        for (int j=0;j<2;j++)
            wmma::store_matrix_sync(stg + (wm*32 + i*16)*68 + wn*32 + j*16, acc[i][j], 68, wmma::mem_row_major);
    __syncthreads();

    if (mode == 1) {
        #pragma unroll
        for (int i=0;i<32;i++){
            int lin = tid + i*256;
            int row = lin >> 6, col = lin & 63;
            int m = m0 + row, n = n0 + col;
            out[(size_t)m*768 + n] = stg[row*68 + col] + bias[n];
        }
    } else {
        // head-split layout + optional RoPE, 2 adjacent cols per thread (rope pair)
        const int h = n0 >> 6;   // BN == 64 == DH, tile == exactly one head
        #pragma unroll
        for (int i=0;i<16;i++){
            int lin = tid + i*256;
            int row = lin >> 5, cp = lin & 31;
            int col = cp * 2;
            int m = m0 + row;
            int b = m / SS, s = m % SS;
            float v0 = stg[row*68 + col]     + bias[n0 + col];
            float v1 = stg[row*68 + col + 1] + bias[n0 + col + 1];
            if (do_rope){
                float t0 = rope[(size_t)(b*SS + s)*DHH + col];
                float t1 = rope[(size_t)(b*SS + s)*DHH + col + 1];
                float c0, s0, c1, s1;
                sincosf(t0, &s0, &c0);
                sincosf(t1, &s1, &c1);
                float o0 = v0*c0 - v1*s0;
                float o1 = v1*c1 + v0*s1;
                v0 = o0; v1 = o1;
            }
            float* dst = out + (((size_t)(b*HH + h)*SS) + s)*DHH + col;
            dst[0] = v0; dst[1] = v1;
        }
    }
}

// ---------------------------------------------------------------------------
// Attention: per (b, h, q-tile of 64 rows). Whole 64x784 score strip in SMEM.
// K/V tiles of 112 rows (7 tiles, 784 exact -> no masking).
// 128 threads (4 warps, each owns 16 q-rows).
// ---------------------------------------------------------------------------
#define QT 64
#define KT 112
#define NKT 7
#define KVLD 68

__global__ __launch_bounds__(128) void attn_kernel()
{
    extern __shared__ float sm[];
    float* scores = sm;                 // 64 x 784
    float* kv     = sm + QT*SS;         // 112 x 68

    const int tid  = threadIdx.x;
    const int warp = tid >> 5;
    const int q0   = blockIdx.x * QT;
    const int h    = blockIdx.y;
    const int b    = blockIdx.z;
    const float scale = 0.125f;  // 64^-0.5
    const size_t base = ((size_t)(b*HH + h)) * SS * DHH;

    // ---- load q tile (scaled) into kv staging ----
    #pragma unroll
    for (int i=0;i<8;i++){
        int lin = tid + i*128;
        int row = lin >> 4, c4 = (lin & 15) * 4;
        int s = q0 + row;
        float4 v = make_float4(0.f,0.f,0.f,0.f);
        if (s < SS) v = *(const float4*)(g_q + base + (size_t)s*DHH + c4);
        v.x *= scale; v.y *= scale; v.z *= scale; v.w *= scale;
        *(float4*)(kv + row*KVLD + c4) = v;
    }
    __syncthreads();

    // persistent q fragments (16 rows x 64, 8 k-chunks)
    wmma::fragment<wmma::matrix_a,16,16,8,wmma::precision::tf32,wmma::row_major> qf[8];
    #pragma unroll
    for (int kk=0;kk<8;kk++){
        wmma::load_matrix_sync(qf[kk], kv + (warp*16)*KVLD + kk*8, KVLD);
        #pragma unroll
        for (int t=0;t<qf[kk].num_elements;t++) qf[kk].x[t] = wmma::__float_to_tf32(qf[kk].x[t]);
    }
    __syncthreads();

    // ---- scores = (q*scale) @ k^T, tile by tile ----
    for (int t=0;t<NKT;t++){
        #pragma unroll
        for (int i=0;i<14;i++){
            int lin = tid + i*128;
            int row = lin >> 4, c4 = (lin & 15) * 4;
            float4 v = *(const float4*)(g_k + base + (size_t)(t*KT + row)*DHH + c4);
            *(float4*)(kv + row*KVLD + c4) = v;
        }
        __syncthreads();

        #pragma unroll
        for (int j=0;j<7;j++){
            wmma::fragment<wmma::accumulator,16,16,8,float> sc;
            wmma::fill_fragment(sc, 0.f);
            #pragma unroll
            for (int kk=0;kk<8;kk++){
                wmma::fragment<wmma::matrix_b,16,16,8,wmma::precision::tf32,wmma::col_major> bf;
                wmma::load_matrix_sync(bf, kv + (j*16)*KVLD + kk*8, KVLD);
                #pragma unroll
                for (int u=0;u<bf.num_elements;u++) bf.x[u] = wmma::__float_to_tf32(bf.x[u]);
                wmma::mma_sync(sc, qf[kk], bf, sc);
            }
            wmma::store_matrix_sync(scores + (warp*16)*SS + t*KT + j*16, sc, SS, wmma::mem_row_major);
        }
        __syncthreads();
    }

    // ---- softmax: 2 threads per row ----
    {
        int r = tid >> 1, halfv = tid & 1;
        float* p = scores + (size_t)r*SS;
        int c0 = halfv * 392, c1 = c0 + 392;
        float mx = -1e30f;
        for (int c=c0;c<c1;c++) mx = fmaxf(mx, p[c]);
        mx = fmaxf(mx, __shfl_xor_sync(0xffffffffu, mx, 1));
        float sum = 0.f;
        for (int c=c0;c<c1;c++){ float e = __expf(p[c] - mx); p[c] = e; sum += e; }
        sum += __shfl_xor_sync(0xffffffffu, sum, 1);
        float inv = 1.f / sum;
        for (int c=c0;c<c1;c++) p[c] *= inv;
    }
    __syncthreads();

    // ---- out = P @ V ----
    wmma::fragment<wmma::accumulator,16,16,8,float> oacc[4];
    #pragma unroll
    for (int j=0;j<4;j++) wmma::fill_fragment(oacc[j], 0.f);

    for (int t=0;t<NKT;t++){
        #pragma unroll
        for (int i=0;i<14;i++){
            int lin = tid + i*128;
            int row = lin >> 4, c4 = (lin & 15) * 4;
            float4 v = *(const float4*)(g_v + base + (size_t)(t*KT + row)*DHH + c4);
            *(float4*)(kv + row*KVLD + c4) = v;
        }
        __syncthreads();

        #pragma unroll
        for (int kk=0;kk<14;kk++){
            wmma::fragment<wmma::matrix_a,16,16,8,wmma::precision::tf32,wmma::row_major> pf;
            wmma::load_matrix_sync(pf, scores + (warp*16)*SS + t*KT + kk*8, SS);
            #pragma unroll
            for (int u=0;u<pf.num_elements;u++) pf.x[u] = wmma::__float_to_tf32(pf.x[u]);
            #pragma unroll
            for (int j=0;j<4;j++){
                wmma::fragment<wmma::matrix_b,16,16,8,wmma::precision::tf32,wmma::row_major> bf;
                wmma::load_matrix_sync(bf, kv + (kk*8)*KVLD + j*16, KVLD);
                #pragma unroll
                for (int u=0;u<bf.num_elements;u++) bf.x[u] = wmma::__float_to_tf32(bf.x[u]);
                wmma::mma_sync(oacc[j], pf, bf, oacc[j]);
            }
        }
        __syncthreads();
    }

    // ---- store context directly in [B,S,D] ----
    #pragma unroll
    for (int j=0;j<4;j++)
        wmma::store_matrix_sync(kv + (warp*16)*KVLD + j*16, oacc[j], KVLD, wmma::mem_row_major);
    __syncthreads();
    #pragma unroll
    for (int i=0;i<32;i++){
        int lin = tid + i*128;
        int row = lin >> 6, col = lin & 63;
        int s = q0 + row;
        if (s < SS)
            g_ctx[((size_t)b*SS + s)*DD + h*DHH + col] = kv[row*KVLD + col];
    }
}

// ---------------------------------------------------------------------------
extern "C" void kernel_launch(void* const* d_in, const int* in_sizes, int n_in,
                              void* d_out, int out_size)
{
    const float* hs   = (const float*)d_in[0];
    const float* rope = (const float*)d_in[1];
    const float* wq   = (const float*)d_in[2];
    const float* bq   = (const float*)d_in[3];
    const float* wk   = (const float*)d_in[4];
    const float* bk   = (const float*)d_in[5];
    const float* wv   = (const float*)d_in[6];
    const float* bv   = (const float*)d_in[7];
    const float* wo   = (const float*)d_in[8];
    const float* bo   = (const float*)d_in[9];
    float* out = (float*)d_out;

    float *q, *k, *v, *ctx;
    cudaGetSymbolAddress((void**)&q,   g_q);
    cudaGetSymbolAddress((void**)&k,   g_k);
    cudaGetSymbolAddress((void**)&v,   g_v);
    cudaGetSymbolAddress((void**)&ctx, g_ctx);

    const size_t gemm_smem = 128*68*sizeof(float);          // 34,816 B (stg dominates)
    const size_t attn_smem = (QT*SS + KT*KVLD)*sizeof(float); // 231,168 B

    cudaFuncSetAttribute(attn_kernel, cudaFuncAttributeMaxDynamicSharedMemorySize, (int)attn_smem);

    dim3 ggrid(12, 98);
    gemm_kernel<<<ggrid, 256, gemm_smem>>>(hs, wq, bq, rope, q, 0, 1);
    gemm_kernel<<<ggrid, 256, gemm_smem>>>(hs, wk, bk, rope, k, 0, 1);
    gemm_kernel<<<ggrid, 256, gemm_smem>>>(hs, wv, bv, rope, v, 0, 0);

    attn_kernel<<<dim3(13, HH, BB), 128, attn_smem>>>();

    gemm_kernel<<<ggrid, 256, gemm_smem>>>(ctx, wo, bo, nullptr, out, 1, 0);
}

// round 2
// speedup vs baseline: 1.1070x; 1.1070x over previous
#include <cuda_runtime.h>
#include <mma.h>
#include <math.h>

using namespace nvcuda;

#define BB 16
#define SS 784
#define DD 768
#define HH 12
#define DHH 64

__device__ float g_q[BB*HH*SS*DHH];
__device__ float g_k[BB*HH*SS*DHH];
__device__ float g_v[BB*HH*SS*DHH];
__device__ float g_ctx[BB*SS*DD];

__device__ __forceinline__ void cpasync16(float* smem, const float* g){
    unsigned s = (unsigned)__cvta_generic_to_shared(smem);
    asm volatile("cp.async.cg.shared.global [%0], [%1], 16;\n" :: "r"(s), "l"(g));
}

// ---------------------------------------------------------------------------
// GEMM: out = A[M,768] @ W[768,768]^T + bias, block tile 128x128, BK=32,
// 256 threads (8 warps as 2x4, warp tile 64x32), cp.async double buffered.
// mode 0: head-split [B,H,S,DH] output + optional RoPE.  mode 1: plain [M,768].
// ---------------------------------------------------------------------------
__global__ __launch_bounds__(256) void gemm_kernel(
    const float* __restrict__ A, const float* __restrict__ W,
    const float* __restrict__ bias, const float* __restrict__ rope,
    float* __restrict__ out, int mode, int do_rope)
{
    extern __shared__ float sm[];
    float* aS[2] = { sm,                sm + 9216 };
    float* bS[2] = { sm + 128*36,       sm + 9216 + 128*36 };

    const int tid  = threadIdx.x;
    const int warp = tid >> 5;
    const int lane = tid & 31;
    const int wm   = warp >> 2;    // 0..1  (64 rows)
    const int wn   = warp & 3;     // 0..3  (32 cols)
    const int m0   = blockIdx.y * 128;
    const int n0   = blockIdx.x * 128;

    wmma::fragment<wmma::accumulator,16,16,8,float> acc[4][2];
    #pragma unroll
    for (int i=0;i<4;i++)
        #pragma unroll
        for (int j=0;j<2;j++)
            wmma::fill_fragment(acc[i][j], 0.f);

    // prologue: stage 0
    {
        #pragma unroll
        for (int i=0;i<4;i++){
            int lin = tid + i*256;
            int row = lin >> 3, c4 = (lin & 7) * 4;
            cpasync16(aS[0] + row*36 + c4, A + (size_t)(m0+row)*768 + c4);
            cpasync16(bS[0] + row*36 + c4, W + (size_t)(n0+row)*768 + c4);
        }
        asm volatile("cp.async.commit_group;\n"::);
    }

    for (int it=0; it<24; ++it){
        int st = it & 1;
        if (it < 23){
            int k0 = (it+1)*32;
            #pragma unroll
            for (int i=0;i<4;i++){
                int lin = tid + i*256;
                int row = lin >> 3, c4 = (lin & 7) * 4;
                cpasync16(aS[st^1] + row*36 + c4, A + (size_t)(m0+row)*768 + k0 + c4);
                cpasync16(bS[st^1] + row*36 + c4, W + (size_t)(n0+row)*768 + k0 + c4);
            }
            asm volatile("cp.async.commit_group;\n"::);
            asm volatile("cp.async.wait_group 1;\n"::);
        } else {
            asm volatile("cp.async.wait_group 0;\n"::);
        }
        __syncthreads();

        #pragma unroll
        for (int kk=0;kk<4;kk++){
            wmma::fragment<wmma::matrix_a,16,16,8,wmma::precision::tf32,wmma::row_major> af[4];
            wmma::fragment<wmma::matrix_b,16,16,8,wmma::precision::tf32,wmma::col_major> bf[2];
            #pragma unroll
            for (int i=0;i<4;i++){
                wmma::load_matrix_sync(af[i], aS[st] + (wm*64 + i*16)*36 + kk*8, 36);
                #pragma unroll
                for (int t=0;t<af[i].num_elements;t++) af[i].x[t] = wmma::__float_to_tf32(af[i].x[t]);
            }
            #pragma unroll
            for (int j=0;j<2;j++){
                wmma::load_matrix_sync(bf[j], bS[st] + (wn*32 + j*16)*36 + kk*8, 36);
                #pragma unroll
                for (int t=0;t<bf[j].num_elements;t++) bf[j].x[t] = wmma::__float_to_tf32(bf[j].x[t]);
            }
            #pragma unroll
            for (int i=0;i<4;i++)
                #pragma unroll
                for (int j=0;j<2;j++)
                    wmma::mma_sync(acc[i][j], af[i], bf[j], acc[i][j]);
        }
        __syncthreads();
    }

    // epilogue: per-warp frag staging (16x20 scratch per warp)
    float* ws = sm + warp * (16*20);
    #pragma unroll
    for (int i=0;i<4;i++){
        #pragma unroll
        for (int j=0;j<2;j++){
            wmma::store_matrix_sync(ws, acc[i][j], 20, wmma::mem_row_major);
            __syncwarp();
            int row  = lane >> 1;
            int cbase = (lane & 1) * 8;
            int m = m0 + wm*64 + i*16 + row;
            int nbase = n0 + wn*32 + j*16 + cbase;
            if (mode == 1){
                #pragma unroll
                for (int cc=0;cc<8;cc++){
                    int n = nbase + cc;
                    out[(size_t)m*768 + n] = ws[row*20 + cbase + cc] + bias[n];
                }
            } else {
                int b = m / SS, s = m % SS;
                #pragma unroll
                for (int p=0;p<4;p++){
                    int n = nbase + p*2;
                    int h = n >> 6, col = n & 63;
                    float v0 = ws[row*20 + cbase + p*2]     + bias[n];
                    float v1 = ws[row*20 + cbase + p*2 + 1] + bias[n+1];
                    if (do_rope){
                        float t0 = rope[(size_t)(b*SS + s)*DHH + col];
                        float t1 = rope[(size_t)(b*SS + s)*DHH + col + 1];
                        float c0, s0, c1, s1;
                        sincosf(t0, &s0, &c0);
                        sincosf(t1, &s1, &c1);
                        float o0 = v0*c0 - v1*s0;
                        float o1 = v1*c1 + v0*s1;
                        v0 = o0; v1 = o1;
                    }
                    float* dst = out + (((size_t)(b*HH + h)*SS) + s)*DHH + col;
                    dst[0] = v0; dst[1] = v1;
                }
            }
            __syncwarp();
        }
    }
}

// ---------------------------------------------------------------------------
// Attention: per (b, h, q-tile of 64). Full 64x784 score strip in SMEM.
// 256 threads (8 warps): wm=warp>>1 owns 16 q-rows, wn=warp&1 splits cols.
// ---------------------------------------------------------------------------
#define QT 64
#define KT 112
#define NKT 7
#define KVLD 68

__global__ __launch_bounds__(256) void attn_kernel()
{
    extern __shared__ float sm[];
    float* scores = sm;                 // 64 x 784
    float* kv     = sm + QT*SS;         // 112 x 68

    const int tid  = threadIdx.x;
    const int warp = tid >> 5;
    const int wm   = warp >> 1;    // 0..3: q-row group
    const int wn   = warp & 1;     // 0..1: column split
    const int q0   = blockIdx.x * QT;
    const int h    = blockIdx.y;
    const int b    = blockIdx.z;
    const float scale = 0.125f;
    const size_t base = ((size_t)(b*HH + h)) * SS * DHH;

    // ---- q tile (scaled) into kv staging ----
    #pragma unroll
    for (int i=0;i<4;i++){
        int lin = tid + i*256;
        int row = lin >> 4, c4 = (lin & 15) * 4;
        int s = q0 + row;
        float4 v = make_float4(0.f,0.f,0.f,0.f);
        if (s < SS) v = *(const float4*)(g_q + base + (size_t)s*DHH + c4);
        v.x *= scale; v.y *= scale; v.z *= scale; v.w *= scale;
        *(float4*)(kv + row*KVLD + c4) = v;
    }
    __syncthreads();

    wmma::fragment<wmma::matrix_a,16,16,8,wmma::precision::tf32,wmma::row_major> qf[8];
    #pragma unroll
    for (int kk=0;kk<8;kk++){
        wmma::load_matrix_sync(qf[kk], kv + (wm*16)*KVLD + kk*8, KVLD);
        #pragma unroll
        for (int t=0;t<qf[kk].num_elements;t++) qf[kk].x[t] = wmma::__float_to_tf32(qf[kk].x[t]);
    }
    __syncthreads();

    // ---- scores = q @ k^T ----
    const int j_lo = wn ? 4 : 0;
    const int j_hi = wn ? 7 : 4;
    for (int t=0;t<NKT;t++){
        #pragma unroll
        for (int i=0;i<7;i++){
            int lin = tid + i*256;
            int row = lin >> 4, c4 = (lin & 15) * 4;
            float4 v = *(const float4*)(g_k + base + (size_t)(t*KT + row)*DHH + c4);
            *(float4*)(kv + row*KVLD + c4) = v;
        }
        __syncthreads();

        for (int j=j_lo;j<j_hi;j++){
            wmma::fragment<wmma::accumulator,16,16,8,float> sc;
            wmma::fill_fragment(sc, 0.f);
            #pragma unroll
            for (int kk=0;kk<8;kk++){
                wmma::fragment<wmma::matrix_b,16,16,8,wmma::precision::tf32,wmma::col_major> bf;
                wmma::load_matrix_sync(bf, kv + (j*16)*KVLD + kk*8, KVLD);
                #pragma unroll
                for (int u=0;u<bf.num_elements;u++) bf.x[u] = wmma::__float_to_tf32(bf.x[u]);
                wmma::mma_sync(sc, qf[kk], bf, sc);
            }
            wmma::store_matrix_sync(scores + (wm*16)*SS + t*KT + j*16, sc, SS, wmma::mem_row_major);
        }
        __syncthreads();
    }

    // ---- softmax: 4 threads per row (196 cols each) ----
    {
        int r = tid >> 2, quad = tid & 3;
        float* p = scores + (size_t)r*SS;
        int c0 = quad * 196, c1 = c0 + 196;
        float mx = -1e30f;
        for (int c=c0;c<c1;c++) mx = fmaxf(mx, p[c]);
        mx = fmaxf(mx, __shfl_xor_sync(0xffffffffu, mx, 1));
        mx = fmaxf(mx, __shfl_xor_sync(0xffffffffu, mx, 2));
        float sum = 0.f;
        for (int c=c0;c<c1;c++){ float e = __expf(p[c] - mx); p[c] = e; sum += e; }
        sum += __shfl_xor_sync(0xffffffffu, sum, 1);
        sum += __shfl_xor_sync(0xffffffffu, sum, 2);
        float inv = 1.f / sum;
        for (int c=c0;c<c1;c++) p[c] *= inv;
    }
    __syncthreads();

    // ---- out = P @ V (wn splits DH into 2x32) ----
    wmma::fragment<wmma::accumulator,16,16,8,float> oacc[2];
    #pragma unroll
    for (int j=0;j<2;j++) wmma::fill_fragment(oacc[j], 0.f);

    for (int t=0;t<NKT;t++){
        #pragma unroll
        for (int i=0;i<7;i++){
            int lin = tid + i*256;
            int row = lin >> 4, c4 = (lin & 15) * 4;
            float4 v = *(const float4*)(g_v + base + (size_t)(t*KT + row)*DHH + c4);
            *(float4*)(kv + row*KVLD + c4) = v;
        }
        __syncthreads();

        #pragma unroll
        for (int kk=0;kk<14;kk++){
            wmma::fragment<wmma::matrix_a,16,16,8,wmma::precision::tf32,wmma::row_major> pf;
            wmma::load_matrix_sync(pf, scores + (wm*16)*SS + t*KT + kk*8, SS);
            #pragma unroll
            for (int u=0;u<pf.num_elements;u++) pf.x[u] = wmma::__float_to_tf32(pf.x[u]);
            #pragma unroll
            for (int j=0;j<2;j++){
                wmma::fragment<wmma::matrix_b,16,16,8,wmma::precision::tf32,wmma::row_major> bf;
                wmma::load_matrix_sync(bf, kv + (kk*8)*KVLD + wn*32 + j*16, KVLD);
                #pragma unroll
                for (int u=0;u<bf.num_elements;u++) bf.x[u] = wmma::__float_to_tf32(bf.x[u]);
                wmma::mma_sync(oacc[j], pf, bf, oacc[j]);
            }
        }
        __syncthreads();
    }

    #pragma unroll
    for (int j=0;j<2;j++)
        wmma::store_matrix_sync(kv + (wm*16)*KVLD + wn*32 + j*16, oacc[j], KVLD, wmma::mem_row_major);
    __syncthreads();
    #pragma unroll
    for (int i=0;i<16;i++){
        int lin = tid + i*256;
        int row = lin >> 6, col = lin & 63;
        int s = q0 + row;
        if (s < SS)
            g_ctx[((size_t)b*SS + s)*DD + h*DHH + col] = kv[row*KVLD + col];
    }
}

// ---------------------------------------------------------------------------
extern "C" void kernel_launch(void* const* d_in, const int* in_sizes, int n_in,
                              void* d_out, int out_size)
{
    const float* hs   = (const float*)d_in[0];
    const float* rope = (const float*)d_in[1];
    const float* wq   = (const float*)d_in[2];
    const float* bq   = (const float*)d_in[3];
    const float* wk   = (const float*)d_in[4];
    const float* bk   = (const float*)d_in[5];
    const float* wv   = (const float*)d_in[6];
    const float* bv   = (const float*)d_in[7];
    const float* wo   = (const float*)d_in[8];
    const float* bo   = (const float*)d_in[9];
    float* out = (float*)d_out;

    float *q, *k, *v, *ctx;
    cudaGetSymbolAddress((void**)&q,   g_q);
    cudaGetSymbolAddress((void**)&k,   g_k);
    cudaGetSymbolAddress((void**)&v,   g_v);
    cudaGetSymbolAddress((void**)&ctx, g_ctx);

    const size_t gemm_smem = 2 * 9216 * sizeof(float);        // 73,728 B
    const size_t attn_smem = (QT*SS + KT*KVLD)*sizeof(float); // 231,168 B

    static int configured = 0;
    cudaFuncSetAttribute(gemm_kernel, cudaFuncAttributeMaxDynamicSharedMemorySize, (int)gemm_smem);
    cudaFuncSetAttribute(attn_kernel, cudaFuncAttributeMaxDynamicSharedMemorySize, (int)attn_smem);
    (void)configured;

    dim3 ggrid(6, 98);
    gemm_kernel<<<ggrid, 256, gemm_smem>>>(hs, wq, bq, rope, q, 0, 1);
    gemm_kernel<<<ggrid, 256, gemm_smem>>>(hs, wk, bk, rope, k, 0, 1);
    gemm_kernel<<<ggrid, 256, gemm_smem>>>(hs, wv, bv, rope, v, 0, 0);

    attn_kernel<<<dim3(13, HH, BB), 256, attn_smem>>>();

    gemm_kernel<<<ggrid, 256, gemm_smem>>>(ctx, wo, bo, nullptr, out, 1, 0);
}

// round 4
// speedup vs baseline: 1.3398x; 1.2103x over previous
#include <cuda_runtime.h>
#include <mma.h>
#include <math.h>

using namespace nvcuda;

#define BB 16
#define SS 784
#define DD 768
#define HH 12
#define DHH 64
#define M_TOT (BB*SS)

__device__ float g_q[BB*HH*SS*DHH];
__device__ float g_k[BB*HH*SS*DHH];
__device__ float g_v[BB*HH*SS*DHH];
__device__ float g_ctx[BB*SS*DD];
__device__ float g_hsr[M_TOT*DD];       // tf32-rounded hidden_states
__device__ float g_wr[4][DD*DD];        // tf32-rounded wq,wk,wv,wo

__device__ __forceinline__ void cpasync16(float* smem, const float* g){
    unsigned s = (unsigned)__cvta_generic_to_shared(smem);
    asm volatile("cp.async.cg.shared.global [%0], [%1], 16;\n" :: "r"(s), "l"(g));
}

// ---------------------------------------------------------------------------
// Elementwise tf32 RN rounding pass (float4 grid-stride)
// ---------------------------------------------------------------------------
__global__ void round_tf32_kernel(const float* __restrict__ in, float* __restrict__ out, int n4){
    int i = blockIdx.x*blockDim.x + threadIdx.x;
    if (i < n4){
        float4 v = ((const float4*)in)[i];
        v.x = wmma::__float_to_tf32(v.x);
        v.y = wmma::__float_to_tf32(v.y);
        v.z = wmma::__float_to_tf32(v.z);
        v.w = wmma::__float_to_tf32(v.w);
        ((float4*)out)[i] = v;
    }
}

// ---------------------------------------------------------------------------
// GEMM: out = A[M,768] @ W[768,768]^T + bias, block 128x128, BK=32,
// 256 threads (8 warps 2x4, warp tile 64x32), cp.async double buffered.
// A and W are PRE-ROUNDED to tf32 -> no cvt in mainloop.
// mode 0: head-split [B,H,S,DH] output (+RoPE), rounded to tf32.
// mode 1: plain [M,768] f32 output (final).
// ---------------------------------------------------------------------------
__global__ __launch_bounds__(256) void gemm_kernel(
    const float* __restrict__ A, const float* __restrict__ W,
    const float* __restrict__ bias, const float* __restrict__ rope,
    float* __restrict__ out, int mode, int do_rope)
{
    extern __shared__ float sm[];
    float* aS[2] = { sm,                sm + 9216 };
    float* bS[2] = { sm + 128*36,       sm + 9216 + 128*36 };

    const int tid  = threadIdx.x;
    const int warp = tid >> 5;
    const int lane = tid & 31;
    const int wm   = warp >> 2;
    const int wn   = warp & 3;
    const int m0   = blockIdx.y * 128;
    const int n0   = blockIdx.x * 128;

    wmma::fragment<wmma::accumulator,16,16,8,float> acc[4][2];
    #pragma unroll
    for (int i=0;i<4;i++)
        #pragma unroll
        for (int j=0;j<2;j++)
            wmma::fill_fragment(acc[i][j], 0.f);

    {
        #pragma unroll
        for (int i=0;i<4;i++){
            int lin = tid + i*256;
            int row = lin >> 3, c4 = (lin & 7) * 4;
            cpasync16(aS[0] + row*36 + c4, A + (size_t)(m0+row)*768 + c4);
            cpasync16(bS[0] + row*36 + c4, W + (size_t)(n0+row)*768 + c4);
        }
        asm volatile("cp.async.commit_group;\n"::);
    }

    for (int it=0; it<24; ++it){
        int st = it & 1;
        if (it < 23){
            int k0 = (it+1)*32;
            #pragma unroll
            for (int i=0;i<4;i++){
                int lin = tid + i*256;
                int row = lin >> 3, c4 = (lin & 7) * 4;
                cpasync16(aS[st^1] + row*36 + c4, A + (size_t)(m0+row)*768 + k0 + c4);
                cpasync16(bS[st^1] + row*36 + c4, W + (size_t)(n0+row)*768 + k0 + c4);
            }
            asm volatile("cp.async.commit_group;\n"::);
            asm volatile("cp.async.wait_group 1;\n"::);
        } else {
            asm volatile("cp.async.wait_group 0;\n"::);
        }
        __syncthreads();

        #pragma unroll
        for (int kk=0;kk<4;kk++){
            wmma::fragment<wmma::matrix_a,16,16,8,wmma::precision::tf32,wmma::row_major> af[4];
            wmma::fragment<wmma::matrix_b,16,16,8,wmma::precision::tf32,wmma::col_major> bf[2];
            #pragma unroll
            for (int i=0;i<4;i++)
                wmma::load_matrix_sync(af[i], aS[st] + (wm*64 + i*16)*36 + kk*8, 36);
            #pragma unroll
            for (int j=0;j<2;j++)
                wmma::load_matrix_sync(bf[j], bS[st] + (wn*32 + j*16)*36 + kk*8, 36);
            #pragma unroll
            for (int i=0;i<4;i++)
                #pragma unroll
                for (int j=0;j<2;j++)
                    wmma::mma_sync(acc[i][j], af[i], bf[j], acc[i][j]);
        }
        __syncthreads();
    }

    // epilogue
    float* ws = sm + warp * (16*20);
    #pragma unroll
    for (int i=0;i<4;i++){
        #pragma unroll
        for (int j=0;j<2;j++){
            wmma::store_matrix_sync(ws, acc[i][j], 20, wmma::mem_row_major);
            __syncwarp();
            int row  = lane >> 1;
            int cbase = (lane & 1) * 8;
            int m = m0 + wm*64 + i*16 + row;
            int nbase = n0 + wn*32 + j*16 + cbase;
            if (mode == 1){
                #pragma unroll
                for (int cc=0;cc<8;cc++){
                    int n = nbase + cc;
                    out[(size_t)m*768 + n] = ws[row*20 + cbase + cc] + bias[n];
                }
            } else {
                int b = m / SS, s = m % SS;
                #pragma unroll
                for (int p=0;p<4;p++){
                    int n = nbase + p*2;
                    int h = n >> 6, col = n & 63;
                    float v0 = ws[row*20 + cbase + p*2]     + bias[n];
                    float v1 = ws[row*20 + cbase + p*2 + 1] + bias[n+1];
                    if (do_rope){
                        float t0 = rope[(size_t)(b*SS + s)*DHH + col];
                        float t1 = rope[(size_t)(b*SS + s)*DHH + col + 1];
                        float c0, s0, c1, s1;
                        sincosf(t0, &s0, &c0);
                        sincosf(t1, &s1, &c1);
                        float o0 = v0*c0 - v1*s0;
                        float o1 = v1*c1 + v0*s1;
                        v0 = o0; v1 = o1;
                    }
                    float* dst = out + (((size_t)(b*HH + h)*SS) + s)*DHH + col;
                    dst[0] = wmma::__float_to_tf32(v0);
                    dst[1] = wmma::__float_to_tf32(v1);
                }
            }
            __syncwarp();
        }
    }
}

// ---------------------------------------------------------------------------
// Attention. All MMA operands (q/k/v from GEMM epilogue, P from softmax)
// are already tf32-rounded -> zero cvt in mainloops.
// ---------------------------------------------------------------------------
#define QT 64
#define KT 112
#define NKT 7
#define KVLD 68

__global__ __launch_bounds__(256) void attn_kernel()
{
    extern __shared__ float sm[];
    float* scores = sm;                 // 64 x 784
    float* kv     = sm + QT*SS;         // 112 x 68

    const int tid  = threadIdx.x;
    const int warp = tid >> 5;
    const int wm   = warp >> 1;
    const int wn   = warp & 1;
    const int q0   = blockIdx.x * QT;
    const int h    = blockIdx.y;
    const int b    = blockIdx.z;
    const float scale = 0.125f;   // exact power of two: preserves tf32 rounding
    const size_t base = ((size_t)(b*HH + h)) * SS * DHH;

    const int prow = tid >> 4;
    const int pc4  = (tid & 15) * 4;

    // ---- q tile (scaled) ----
    #pragma unroll
    for (int i=0;i<4;i++){
        int lin = tid + i*256;
        int row = lin >> 4, c4 = (lin & 15) * 4;
        int s = q0 + row;
        float4 v = make_float4(0.f,0.f,0.f,0.f);
        if (s < SS) v = *(const float4*)(g_q + base + (size_t)s*DHH + c4);
        v.x *= scale; v.y *= scale; v.z *= scale; v.w *= scale;
        *(float4*)(kv + row*KVLD + c4) = v;
    }
    __syncthreads();

    wmma::fragment<wmma::matrix_a,16,16,8,wmma::precision::tf32,wmma::row_major> qf[8];
    #pragma unroll
    for (int kk=0;kk<8;kk++)
        wmma::load_matrix_sync(qf[kk], kv + (wm*16)*KVLD + kk*8, KVLD);

    float4 pre[7];
    #pragma unroll
    for (int i=0;i<7;i++)
        pre[i] = *(const float4*)(g_k + base + (size_t)(prow + i*16)*DHH + pc4);

    // ---- scores = q @ k^T ----
    const int j_lo = wn ? 4 : 0;
    const int j_hi = wn ? 7 : 4;
    for (int t=0;t<NKT;t++){
        __syncthreads();
        #pragma unroll
        for (int i=0;i<7;i++)
            *(float4*)(kv + (prow + i*16)*KVLD + pc4) = pre[i];
        __syncthreads();
        if (t < NKT-1){
            #pragma unroll
            for (int i=0;i<7;i++)
                pre[i] = *(const float4*)(g_k + base + (size_t)((t+1)*KT + prow + i*16)*DHH + pc4);
        }

        for (int j=j_lo; j<j_hi; j+=2){
            bool two = (j+1 < j_hi);
            wmma::fragment<wmma::accumulator,16,16,8,float> sc0, sc1;
            wmma::fill_fragment(sc0, 0.f);
            wmma::fill_fragment(sc1, 0.f);
            #pragma unroll
            for (int kk=0;kk<8;kk++){
                wmma::fragment<wmma::matrix_b,16,16,8,wmma::precision::tf32,wmma::col_major> bf0, bf1;
                wmma::load_matrix_sync(bf0, kv + (j*16)*KVLD + kk*8, KVLD);
                if (two) wmma::load_matrix_sync(bf1, kv + ((j+1)*16)*KVLD + kk*8, KVLD);
                wmma::mma_sync(sc0, qf[kk], bf0, sc0);
                if (two) wmma::mma_sync(sc1, qf[kk], bf1, sc1);
            }
            wmma::store_matrix_sync(scores + (wm*16)*SS + t*KT + j*16, sc0, SS, wmma::mem_row_major);
            if (two)
                wmma::store_matrix_sync(scores + (wm*16)*SS + t*KT + (j+1)*16, sc1, SS, wmma::mem_row_major);
        }
    }
    __syncthreads();

    // ---- softmax (4 threads/row); P rounded to tf32 in the normalize loop ----
    {
        int r = tid >> 2, quad = tid & 3;
        float* p = scores + (size_t)r*SS;
        int c0 = quad * 196, c1 = c0 + 196;
        float mx = -1e30f;
        for (int c=c0;c<c1;c++) mx = fmaxf(mx, p[c]);
        mx = fmaxf(mx, __shfl_xor_sync(0xffffffffu, mx, 1));
        mx = fmaxf(mx, __shfl_xor_sync(0xffffffffu, mx, 2));
        float sum = 0.f;
        for (int c=c0;c<c1;c++){ float e = __expf(p[c] - mx); p[c] = e; sum += e; }
        sum += __shfl_xor_sync(0xffffffffu, sum, 1);
        sum += __shfl_xor_sync(0xffffffffu, sum, 2);
        float inv = 1.f / sum;
        for (int c=c0;c<c1;c++) p[c] = wmma::__float_to_tf32(p[c] * inv);
    }

    #pragma unroll
    for (int i=0;i<7;i++)
        pre[i] = *(const float4*)(g_v + base + (size_t)(prow + i*16)*DHH + pc4);

    // ---- out = P @ V ----
    wmma::fragment<wmma::accumulator,16,16,8,float> oacc[2][2];
    #pragma unroll
    for (int j=0;j<2;j++)
        #pragma unroll
        for (int p=0;p<2;p++)
            wmma::fill_fragment(oacc[j][p], 0.f);

    for (int t=0;t<NKT;t++){
        __syncthreads();
        #pragma unroll
        for (int i=0;i<7;i++)
            *(float4*)(kv + (prow + i*16)*KVLD + pc4) = pre[i];
        __syncthreads();
        if (t < NKT-1){
            #pragma unroll
            for (int i=0;i<7;i++)
                pre[i] = *(const float4*)(g_v + base + (size_t)((t+1)*KT + prow + i*16)*DHH + pc4);
        }

        #pragma unroll
        for (int kk=0;kk<14;kk++){
            int par = kk & 1;
            wmma::fragment<wmma::matrix_a,16,16,8,wmma::precision::tf32,wmma::row_major> pf;
            wmma::load_matrix_sync(pf, scores + (wm*16)*SS + t*KT + kk*8, SS);
            #pragma unroll
            for (int j=0;j<2;j++){
                wmma::fragment<wmma::matrix_b,16,16,8,wmma::precision::tf32,wmma::row_major> bf;
                wmma::load_matrix_sync(bf, kv + (kk*8)*KVLD + wn*32 + j*16, KVLD);
                wmma::mma_sync(oacc[j][par], pf, bf, oacc[j][par]);
            }
        }
    }

    #pragma unroll
    for (int j=0;j<2;j++)
        #pragma unroll
        for (int u=0;u<oacc[j][0].num_elements;u++)
            oacc[j][0].x[u] += oacc[j][1].x[u];

    __syncthreads();
    #pragma unroll
    for (int j=0;j<2;j++)
        wmma::store_matrix_sync(kv + (wm*16)*KVLD + wn*32 + j*16, oacc[j][0], KVLD, wmma::mem_row_major);
    __syncthreads();
    #pragma unroll
    for (int i=0;i<16;i++){
        int lin = tid + i*256;
        int row = lin >> 6, col = lin & 63;
        int s = q0 + row;
        if (s < SS)
            g_ctx[((size_t)b*SS + s)*DD + h*DHH + col] = wmma::__float_to_tf32(kv[row*KVLD + col]);
    }
}

// ---------------------------------------------------------------------------
extern "C" void kernel_launch(void* const* d_in, const int* in_sizes, int n_in,
                              void* d_out, int out_size)
{
    const float* hs   = (const float*)d_in[0];
    const float* rope = (const float*)d_in[1];
    const float* wq   = (const float*)d_in[2];
    const float* bq   = (const float*)d_in[3];
    const float* wk   = (const float*)d_in[4];
    const float* bk   = (const float*)d_in[5];
    const float* wv   = (const float*)d_in[6];
    const float* bv   = (const float*)d_in[7];
    const float* wo   = (const float*)d_in[8];
    const float* bo   = (const float*)d_in[9];
    float* out = (float*)d_out;

    float *q, *k, *v, *ctx, *hsr, *wr;
    cudaGetSymbolAddress((void**)&q,   g_q);
    cudaGetSymbolAddress((void**)&k,   g_k);
    cudaGetSymbolAddress((void**)&v,   g_v);
    cudaGetSymbolAddress((void**)&ctx, g_ctx);
    cudaGetSymbolAddress((void**)&hsr, g_hsr);
    cudaGetSymbolAddress((void**)&wr,  g_wr);

    float* wqr = wr;
    float* wkr = wr + DD*DD;
    float* wvr = wr + 2*DD*DD;
    float* wor = wr + 3*DD*DD;

    const size_t gemm_smem = 2 * 9216 * sizeof(float);
    const size_t attn_smem = (QT*SS + KT*KVLD)*sizeof(float);

    cudaFuncSetAttribute(gemm_kernel, cudaFuncAttributeMaxDynamicSharedMemorySize, (int)gemm_smem);
    cudaFuncSetAttribute(attn_kernel, cudaFuncAttributeMaxDynamicSharedMemorySize, (int)attn_smem);

    // pre-round inputs to tf32 (RN)
    {
        int n4h = (M_TOT*DD)/4, n4w = (DD*DD)/4;
        round_tf32_kernel<<<(n4h+255)/256, 256>>>(hs, hsr, n4h);
        round_tf32_kernel<<<(n4w+255)/256, 256>>>(wq, wqr, n4w);
        round_tf32_kernel<<<(n4w+255)/256, 256>>>(wk, wkr, n4w);
        round_tf32_kernel<<<(n4w+255)/256, 256>>>(wv, wvr, n4w);
        round_tf32_kernel<<<(n4w+255)/256, 256>>>(wo, wor, n4w);
    }

    dim3 ggrid(6, 98);
    gemm_kernel<<<ggrid, 256, gemm_smem>>>(hsr, wqr, bq, rope, q, 0, 1);
    gemm_kernel<<<ggrid, 256, gemm_smem>>>(hsr, wkr, bk, rope, k, 0, 1);
    gemm_kernel<<<ggrid, 256, gemm_smem>>>(hsr, wvr, bv, rope, v, 0, 0);

    attn_kernel<<<dim3(13, HH, BB), 256, attn_smem>>>();

    gemm_kernel<<<ggrid, 256, gemm_smem>>>(ctx, wor, bo, nullptr, out, 1, 0);
}